// round 9
// baseline (speedup 1.0000x reference)
#include <cuda_runtime.h>
#include <cuda_fp16.h>

#define HEADS 8
#define D 256
#define NCAP 32768
#define MCAP 327680
#define TCAP 65536
#define TILE_E 8

// Segment-sum scratch, packed: seg[(node*b + bb)*HEADS + h]. 2MB slack.
__device__ float g_seg[1 << 19];

// fp16 mirrors of q and k.
#define QK_CAP 10485760
__device__ __half g_qh[QK_CAP];
__device__ __half g_kh[QK_CAP];

// counting-sort / CSR / tile scratch
__device__ int  g_cnt[NCAP];    // per-q-node edge count (zeroed by tile kernel)
__device__ int  g_ofs[NCAP];    // CSR row start, +sentinel at [n]
__device__ int  g_cur[NCAP];    // scatter cursor (mutated)
__device__ int2 g_edges[MCAP];  // {ki, original_edge_idx} grouped by q-node
__device__ int  g_ntile;        // tile counter (zeroed by scan)
__device__ int4 g_tiles[TCAP];  // {node, edge_start, edge_cnt<=8, 0}

// Convert q,k -> fp16; zero seg; histogram e0. g_cnt was zeroed by the
// previous call's tile kernel (or static zero-init on first call).
__global__ void __launch_bounds__(256) prep_kernel(
    const float4* __restrict__ q, const float4* __restrict__ k,
    const int* __restrict__ e0, int m, int n16, int segcount)
{
    int i = blockIdx.x * blockDim.x + threadIdx.x;
    int stride = gridDim.x * blockDim.x;

    for (int s = i; s < segcount; s += stride) g_seg[s] = 0.0f;
    for (int j = i; j < m; j += stride) atomicAdd(&g_cnt[e0[j]], 1);

    uint4* qh = (uint4*)g_qh;
    uint4* kh = (uint4*)g_kh;
    for (int j = i; j < n16; j += stride) {
        float4 v0 = q[2 * j], v1 = q[2 * j + 1];
        __half2 h0 = __floats2half2_rn(v0.x, v0.y);
        __half2 h1 = __floats2half2_rn(v0.z, v0.w);
        __half2 h2 = __floats2half2_rn(v1.x, v1.y);
        __half2 h3 = __floats2half2_rn(v1.z, v1.w);
        uint4 u;
        u.x = *(unsigned*)&h0; u.y = *(unsigned*)&h1;
        u.z = *(unsigned*)&h2; u.w = *(unsigned*)&h3;
        qh[j] = u;

        v0 = k[2 * j]; v1 = k[2 * j + 1];
        h0 = __floats2half2_rn(v0.x, v0.y);
        h1 = __floats2half2_rn(v0.z, v0.w);
        h2 = __floats2half2_rn(v1.x, v1.y);
        h3 = __floats2half2_rn(v1.z, v1.w);
        u.x = *(unsigned*)&h0; u.y = *(unsigned*)&h1;
        u.z = *(unsigned*)&h2; u.w = *(unsigned*)&h3;
        kh[j] = u;
    }
}

// Single-block exclusive scan of g_cnt[0..n) -> g_ofs,g_cur; sentinel; ntile=0.
__global__ void __launch_bounds__(1024) scan_kernel(int n)
{
    __shared__ int warpsum[32];
    __shared__ int warpexcl[32];
    __shared__ int carry;
    int tid = threadIdx.x, lane = tid & 31, wid = tid >> 5;
    if (tid == 0) carry = 0;
    __syncthreads();

    for (int base = 0; base < n; base += 1024) {
        int i = base + tid;
        int v = (i < n) ? g_cnt[i] : 0;
        int s = v;
        #pragma unroll
        for (int off = 1; off < 32; off <<= 1) {
            int t = __shfl_up_sync(0xffffffffu, s, off);
            if (lane >= off) s += t;
        }
        if (lane == 31) warpsum[wid] = s;
        __syncthreads();
        if (wid == 0) {
            int w = warpsum[lane];
            int ws = w;
            #pragma unroll
            for (int off = 1; off < 32; off <<= 1) {
                int t = __shfl_up_sync(0xffffffffu, ws, off);
                if (lane >= off) ws += t;
            }
            warpexcl[lane] = ws - w;
        }
        __syncthreads();
        int excl = (s - v) + warpexcl[wid] + carry;
        if (i < n) { g_ofs[i] = excl; g_cur[i] = excl; }
        __syncthreads();
        if (tid == 0) carry += warpexcl[31] + warpsum[31];
        __syncthreads();
    }
    if (threadIdx.x == 0) { g_ofs[n] = carry; g_ntile = 0; }
}

// One thread per node: emit <=TILE_E-edge tiles; re-zero g_cnt for next call.
__global__ void __launch_bounds__(256) tile_kernel(int n)
{
    int v = blockIdx.x * blockDim.x + threadIdx.x;
    if (v >= n) return;
    int start = g_ofs[v];
    int cnt = g_ofs[v + 1] - start;
    g_cnt[v] = 0;
    for (int t = 0; t < cnt; t += TILE_E) {
        int pos = atomicAdd(&g_ntile, 1);
        int len = cnt - t; if (len > TILE_E) len = TILE_E;
        g_tiles[pos] = make_int4(v, start + t, len, 0);
    }
}

// Scatter edges into q-node-grouped order: {ki, edge_idx}.
__global__ void __launch_bounds__(256) scatter_kernel(
    const int* __restrict__ e0, const int* __restrict__ e1, int m)
{
    int j = blockIdx.x * blockDim.x + threadIdx.x;
    if (j >= m) return;
    int qi = e0[j];
    int pos = atomicAdd(&g_cur[qi], 1);
    g_edges[pos] = make_int2(e1[j], j);
}

__device__ __forceinline__ float dot16(uint4 uq, uint4 uk) {
    float s = 0.0f;
    float2 a, c;
    a = __half22float2(*(const __half2*)&uq.x); c = __half22float2(*(const __half2*)&uk.x);
    s += a.x * c.x + a.y * c.y;
    a = __half22float2(*(const __half2*)&uq.y); c = __half22float2(*(const __half2*)&uk.y);
    s += a.x * c.x + a.y * c.y;
    a = __half22float2(*(const __half2*)&uq.z); c = __half22float2(*(const __half2*)&uk.z);
    s += a.x * c.x + a.y * c.y;
    a = __half22float2(*(const __half2*)&uq.w); c = __half22float2(*(const __half2*)&uk.w);
    s += a.x * c.x + a.y * c.y;
    return s;
}

// A1: one warp per tile (<=8 edges of one q-node). q row (both batches) in
// registers; edges processed in PAIRS -> 4 independent k-row loads in flight.
__global__ void __launch_bounds__(256) passA1_kernel(
    float* __restrict__ ex_out, int n, int m, int b)
{
    int w = blockIdx.x * (blockDim.x >> 5) + (threadIdx.x >> 5);
    int lane = threadIdx.x & 31;
    if (w >= g_ntile) return;

    int4 tl = g_tiles[w];
    int v = tl.x, start = tl.y, cnt = tl.z;

    const uint4* qbase = (const uint4*)g_qh;
    const uint4* kbase = (const uint4*)g_kh;
    long long bstride = (long long)n * (D / 8);
    long long rowq = (long long)v * (D / 8) + lane;

    if (b == 2) {
        uint4 uq0 = qbase[rowq];
        uint4 uq1 = qbase[rowq + bstride];

        for (int t = 0; t < cnt; t += 2) {
            int2 eA = g_edges[start + t];
            bool hasB = (t + 1 < cnt);
            int2 eB = hasB ? g_edges[start + t + 1] : eA;

            long long rowkA = (long long)eA.x * (D / 8) + lane;
            long long rowkB = (long long)eB.x * (D / 8) + lane;
            uint4 ukA0 = kbase[rowkA];
            uint4 ukA1 = kbase[rowkA + bstride];
            uint4 ukB0 = kbase[rowkB];
            uint4 ukB1 = kbase[rowkB + bstride];

            float sA0 = dot16(uq0, ukA0);
            float sA1 = dot16(uq1, ukA1);
            float sB0 = dot16(uq0, ukB0);
            float sB1 = dot16(uq1, ukB1);

            sA0 += __shfl_xor_sync(0xffffffffu, sA0, 1);
            sA1 += __shfl_xor_sync(0xffffffffu, sA1, 1);
            sB0 += __shfl_xor_sync(0xffffffffu, sB0, 1);
            sB1 += __shfl_xor_sync(0xffffffffu, sB1, 1);
            sA0 += __shfl_xor_sync(0xffffffffu, sA0, 2);
            sA1 += __shfl_xor_sync(0xffffffffu, sA1, 2);
            sB0 += __shfl_xor_sync(0xffffffffu, sB0, 2);
            sB1 += __shfl_xor_sync(0xffffffffu, sB1, 2);

            // a = dot/sqrt(256); global max-shift dropped (ratio is
            // shift-invariant, exp(a) <= ~8, eps below fp32 ulp of denom).
            float exA0 = __expf(sA0 * 0.0625f);
            float exA1 = __expf(sA1 * 0.0625f);
            float exB0 = __expf(sB0 * 0.0625f);
            float exB1 = __expf(sB1 * 0.0625f);

            if ((lane & 3) == 0) {
                int h = lane >> 2;
                ex_out[(((long long)eA.y) << 3) + h] = exA0;
                ex_out[(((long long)(m + eA.y)) << 3) + h] = exA1;
                if (hasB) {
                    ex_out[(((long long)eB.y) << 3) + h] = exB0;
                    ex_out[(((long long)(m + eB.y)) << 3) + h] = exB1;
                }
            }
        }
    } else {
        for (int t = 0; t < cnt; t++) {
            int2 ed = g_edges[start + t];
            long long rowk = (long long)ed.x * (D / 8) + lane;
            for (int bb = 0; bb < b; bb++) {
                uint4 uq = qbase[rowq + bb * bstride];
                uint4 uk = kbase[rowk + bb * bstride];
                float s = dot16(uq, uk);
                s += __shfl_xor_sync(0xffffffffu, s, 1);
                s += __shfl_xor_sync(0xffffffffu, s, 2);
                float ex = __expf(s * 0.0625f);
                if ((lane & 3) == 0)
                    ex_out[(((long long)bb * m + ed.y) << 3) + (lane >> 2)] = ex;
            }
        }
    }
}

// A2: pure segment reduction. One thread per 16B ex chunk.
__global__ void __launch_bounds__(256) passA2_kernel(
    const int* __restrict__ r, const float4* __restrict__ ex,
    int m, int b)
{
    int tid = blockIdx.x * blockDim.x + threadIdx.x;
    int total = m * b * 2;
    if (tid >= total) return;
    int bb = tid / (2 * m);
    int rem = tid - bb * 2 * m;
    int mm = rem >> 1;
    int half = rem & 1;
    int rr = r[mm];

    float4 v = ex[tid];

    float* segp = &g_seg[(((long long)rr * b + bb) << 3) + (half << 2)];
    asm volatile("red.global.add.v4.f32 [%0], {%1, %2, %3, %4};"
                 :: "l"(segp), "f"(v.x), "f"(v.y), "f"(v.z), "f"(v.w)
                 : "memory");
}

// B: one thread per (batch, edge): normalize 8 heads.
__global__ void __launch_bounds__(256) passB_kernel(
    const int* __restrict__ r, float* __restrict__ out, int m, int b)
{
    int i = blockIdx.x * blockDim.x + threadIdx.x;
    if (i >= m * b) return;
    int bb = i / m;
    int mm = i - bb * m;
    int rr = r[mm];

    const float4* segp = (const float4*)&g_seg[(((long long)rr * b + bb) << 3)];
    float4 s0 = segp[0], s1 = segp[1];

    float4* op = (float4*)(out + ((long long)i << 3));
    float4 v0 = op[0], v1 = op[1];

    v0.x /= (s0.x + 1e-16f); v0.y /= (s0.y + 1e-16f);
    v0.z /= (s0.z + 1e-16f); v0.w /= (s0.w + 1e-16f);
    v1.x /= (s1.x + 1e-16f); v1.y /= (s1.y + 1e-16f);
    v1.z /= (s1.z + 1e-16f); v1.w /= (s1.w + 1e-16f);

    op[0] = v0; op[1] = v1;
}

extern "C" void kernel_launch(void* const* d_in, const int* in_sizes, int n_in,
                              void* d_out, int out_size) {
    const float* q = (const float*)d_in[0];
    const float* k = (const float*)d_in[1];
    const int*   e = (const int*)d_in[2];
    const int*   r = (const int*)d_in[3];
    float* out = (float*)d_out;

    int m = in_sizes[3];                    // r has m elements
    int b = out_size / (m * HEADS);         // output is (b, m, HEADS)
    int n = in_sizes[0] / (b * D);          // q is (b, n, D)

    const int* e0 = e;
    const int* e1 = e + m;

    int seg_count = n * b * HEADS;
    int n16 = (b * n * D) / 8;              // 16-byte half chunks per tensor
    prep_kernel<<<5000, 256>>>((const float4*)q, (const float4*)k, e0, m, n16, seg_count);

    scan_kernel<<<1, 1024>>>(n);
    tile_kernel<<<(n + 255) / 256, 256>>>(n);
    scatter_kernel<<<(m + 255) / 256, 256>>>(e0, e1, m);

    int max_tiles = n + (m + TILE_E - 1) / TILE_E;   // upper bound; A1 early-exits on g_ntile
    passA1_kernel<<<(max_tiles + 7) / 8, 256>>>(out, n, m, b);

    int mb = m * b;
    int chunks = mb * 2;
    passA2_kernel<<<(chunks + 255) / 256, 256>>>(r, (const float4*)out, m, b);

    passB_kernel<<<(mb + 255) / 256, 256>>>(r, out, m, b);
}

// round 10
// speedup vs baseline: 1.0968x; 1.0968x over previous
#include <cuda_runtime.h>
#include <cuda_fp16.h>

#define HEADS 8
#define D 256
#define NCAP 32768
#define MCAP 327680

// Segment-sum scratch, packed: seg[(node*b + bb)*HEADS + h]. 2MB slack.
__device__ float g_seg[1 << 19];

// fp16 mirror of k only (q is read fp32 from the input, L1-amortized by sort).
#define QK_CAP 10485760
__device__ __half g_kh[QK_CAP];

// counting-sort / CSR scratch
__device__ int  g_cnt[NCAP];    // per-q-node edge count (re-zeroed in scan epilogue kernel)
__device__ int  g_ofs[NCAP];    // CSR row start
__device__ int  g_cur[NCAP];    // scatter cursor (mutated)
__device__ int2 g_edges[MCAP];  // {ki, original_edge_idx} grouped by q-node

// Zero seg; histogram e0; convert k -> fp16. g_cnt is zeroed at the end of
// the previous call's passA1 epilogue... no: zeroed here via first loop each
// call BEFORE hist would race across blocks. Instead g_cnt is re-zeroed by
// scan_kernel's second pass of the PREVIOUS call? Simplest safe scheme:
// hist uses g_cur as the histogram target, zeroed here; g_cnt unused.
__global__ void __launch_bounds__(256) prep_kernel(
    const float4* __restrict__ k,
    const int* __restrict__ e0, int m, int n16, int segcount)
{
    int i = blockIdx.x * blockDim.x + threadIdx.x;
    int stride = gridDim.x * blockDim.x;

    for (int s = i; s < segcount; s += stride) g_seg[s] = 0.0f;

    // histogram into g_cnt, which scan_kernel consumed AND re-zeroes each
    // call is not available first call -> use static zero-init + explicit
    // re-zero in scan_kernel after reading. (g_cnt starts zeroed; scan
    // re-zeroes it after consuming, so it is zero when prep's hist runs.)
    for (int j = i; j < m; j += stride) atomicAdd(&g_cnt[e0[j]], 1);

    uint4* kh = (uint4*)g_kh;
    for (int j = i; j < n16; j += stride) {
        float4 v0 = k[2 * j], v1 = k[2 * j + 1];
        __half2 h0 = __floats2half2_rn(v0.x, v0.y);
        __half2 h1 = __floats2half2_rn(v0.z, v0.w);
        __half2 h2 = __floats2half2_rn(v1.x, v1.y);
        __half2 h3 = __floats2half2_rn(v1.z, v1.w);
        uint4 u;
        u.x = *(unsigned*)&h0; u.y = *(unsigned*)&h1;
        u.z = *(unsigned*)&h2; u.w = *(unsigned*)&h3;
        kh[j] = u;
    }
}

// Single-block exclusive scan of g_cnt[0..n) -> g_ofs,g_cur.
// Also RE-ZEROES g_cnt after reading (so prep's histogram next call starts
// from zero) and keeps per-node count in g_ofs[v+1]-g_ofs[v] via sentinel.
__global__ void __launch_bounds__(1024) scan_kernel(int n)
{
    __shared__ int warpsum[32];
    __shared__ int warpexcl[32];
    __shared__ int carry;
    int tid = threadIdx.x, lane = tid & 31, wid = tid >> 5;
    if (tid == 0) carry = 0;
    __syncthreads();

    for (int base = 0; base < n; base += 1024) {
        int i = base + tid;
        int v = (i < n) ? g_cnt[i] : 0;
        if (i < n) g_cnt[i] = 0;           // reset for next call's histogram
        int s = v;
        #pragma unroll
        for (int off = 1; off < 32; off <<= 1) {
            int t = __shfl_up_sync(0xffffffffu, s, off);
            if (lane >= off) s += t;
        }
        if (lane == 31) warpsum[wid] = s;
        __syncthreads();
        if (wid == 0) {
            int w = warpsum[lane];
            int ws = w;
            #pragma unroll
            for (int off = 1; off < 32; off <<= 1) {
                int t = __shfl_up_sync(0xffffffffu, ws, off);
                if (lane >= off) ws += t;
            }
            warpexcl[lane] = ws - w;
        }
        __syncthreads();
        int excl = (s - v) + warpexcl[wid] + carry;
        if (i < n) { g_ofs[i] = excl; g_cur[i] = excl; }
        __syncthreads();
        if (tid == 0) carry += warpexcl[31] + warpsum[31];
        __syncthreads();
    }
    if (threadIdx.x == 0) g_ofs[n] = carry;   // sentinel
}

// Scatter edges into q-node-grouped order: {ki, edge_idx}. 4 edges per
// thread with vectorized index loads -> 4 atomic/store chains in flight.
__global__ void __launch_bounds__(256) scatter_kernel(
    const int* __restrict__ e0, const int* __restrict__ e1, int m)
{
    int t = blockIdx.x * blockDim.x + threadIdx.x;
    int j0 = t * 4;
    if (j0 >= m) return;

    if (j0 + 4 <= m) {
        int4 q4 = *(const int4*)(e0 + j0);
        int4 k4 = *(const int4*)(e1 + j0);
        int p0 = atomicAdd(&g_cur[q4.x], 1);
        int p1 = atomicAdd(&g_cur[q4.y], 1);
        int p2 = atomicAdd(&g_cur[q4.z], 1);
        int p3 = atomicAdd(&g_cur[q4.w], 1);
        g_edges[p0] = make_int2(k4.x, j0 + 0);
        g_edges[p1] = make_int2(k4.y, j0 + 1);
        g_edges[p2] = make_int2(k4.z, j0 + 2);
        g_edges[p3] = make_int2(k4.w, j0 + 3);
    } else {
        for (int j = j0; j < m; j++) {
            int pos = atomicAdd(&g_cur[e0[j]], 1);
            g_edges[pos] = make_int2(e1[j], j);
        }
    }
}

// mixed dot: 8 fp32 q elements (2 float4) x 8 fp16 k elements (uint4)
__device__ __forceinline__ float dotqk(float4 qa, float4 qb, uint4 uk) {
    float s = 0.0f;
    float2 c;
    c = __half22float2(*(const __half2*)&uk.x); s += qa.x * c.x + qa.y * c.y;
    c = __half22float2(*(const __half2*)&uk.y); s += qa.z * c.x + qa.w * c.y;
    c = __half22float2(*(const __half2*)&uk.z); s += qb.x * c.x + qb.y * c.y;
    c = __half22float2(*(const __half2*)&uk.w); s += qb.z * c.x + qb.w * c.y;
    return s;
}

// A1: one warp per q-node. q row (both batches, fp32 from input) loaded once
// into registers; loop over the node's edges loads fp16 k rows (2 per edge)
// with a 1-deep edge-record prefetch. No atomics.
__global__ void __launch_bounds__(256) passA1_kernel(
    const float4* __restrict__ q,
    float* __restrict__ ex_out, int n, int m, int b)
{
    int v = blockIdx.x * (blockDim.x >> 5) + (threadIdx.x >> 5);
    int lane = threadIdx.x & 31;
    if (v >= n) return;

    int start = g_ofs[v];
    int cnt = g_ofs[v + 1] - start;
    if (cnt == 0) return;

    const uint4* kbase = (const uint4*)g_kh;
    long long kbstride = (long long)n * (D / 8);
    long long qrow = (long long)v * (D / 4) + lane * 2;
    long long qbstride = (long long)n * (D / 4);

    if (b == 2) {
        float4 qa0 = q[qrow],            qb0 = q[qrow + 1];
        float4 qa1 = q[qrow + qbstride], qb1 = q[qrow + qbstride + 1];

        int2 ed = g_edges[start];
        for (int t = 0; t < cnt; t++) {
            int ki = ed.x, j = ed.y;
            long long rowk = (long long)ki * (D / 8) + lane;
            uint4 uk0 = kbase[rowk];
            uint4 uk1 = kbase[rowk + kbstride];
            if (t + 1 < cnt) ed = g_edges[start + t + 1];

            float s0 = dotqk(qa0, qb0, uk0);
            float s1 = dotqk(qa1, qb1, uk1);
            s0 += __shfl_xor_sync(0xffffffffu, s0, 1);
            s1 += __shfl_xor_sync(0xffffffffu, s1, 1);
            s0 += __shfl_xor_sync(0xffffffffu, s0, 2);
            s1 += __shfl_xor_sync(0xffffffffu, s1, 2);

            // a = dot/sqrt(256); global max-shift dropped (ratio is
            // shift-invariant, exp(a) <= ~8, eps below fp32 ulp of denom).
            float ex0 = __expf(s0 * 0.0625f);
            float ex1 = __expf(s1 * 0.0625f);

            if ((lane & 3) == 0) {
                int h = lane >> 2;
                ex_out[(((long long)j) << 3) + h] = ex0;
                ex_out[(((long long)(m + j)) << 3) + h] = ex1;
            }
        }
    } else {
        for (int t = 0; t < cnt; t++) {
            int2 ed = g_edges[start + t];
            long long rowk = (long long)ed.x * (D / 8) + lane;
            for (int bb = 0; bb < b; bb++) {
                float4 qa = q[qrow + bb * qbstride];
                float4 qb = q[qrow + bb * qbstride + 1];
                uint4 uk = kbase[rowk + bb * kbstride];
                float s = dotqk(qa, qb, uk);
                s += __shfl_xor_sync(0xffffffffu, s, 1);
                s += __shfl_xor_sync(0xffffffffu, s, 2);
                float ex = __expf(s * 0.0625f);
                if ((lane & 3) == 0)
                    ex_out[(((long long)bb * m + ed.y) << 3) + (lane >> 2)] = ex;
            }
        }
    }
}

// A2: pure segment reduction. One thread per 16B ex chunk: stream-read ex,
// one red.global.add.v4.f32 into the packed seg table.
__global__ void __launch_bounds__(256) passA2_kernel(
    const int* __restrict__ r, const float4* __restrict__ ex,
    int m, int b)
{
    int tid = blockIdx.x * blockDim.x + threadIdx.x;
    int total = m * b * 2;
    if (tid >= total) return;
    int bb = tid / (2 * m);
    int rem = tid - bb * 2 * m;
    int mm = rem >> 1;
    int half = rem & 1;
    int rr = r[mm];

    float4 v = ex[tid];

    float* segp = &g_seg[(((long long)rr * b + bb) << 3) + (half << 2)];
    asm volatile("red.global.add.v4.f32 [%0], {%1, %2, %3, %4};"
                 :: "l"(segp), "f"(v.x), "f"(v.y), "f"(v.z), "f"(v.w)
                 : "memory");
}

// B: one thread per (batch, edge): normalize 8 heads.
__global__ void __launch_bounds__(256) passB_kernel(
    const int* __restrict__ r, float* __restrict__ out, int m, int b)
{
    int i = blockIdx.x * blockDim.x + threadIdx.x;
    if (i >= m * b) return;
    int bb = i / m;
    int mm = i - bb * m;
    int rr = r[mm];

    const float4* segp = (const float4*)&g_seg[(((long long)rr * b + bb) << 3)];
    float4 s0 = segp[0], s1 = segp[1];

    float4* op = (float4*)(out + ((long long)i << 3));
    float4 v0 = op[0], v1 = op[1];

    v0.x /= (s0.x + 1e-16f); v0.y /= (s0.y + 1e-16f);
    v0.z /= (s0.z + 1e-16f); v0.w /= (s0.w + 1e-16f);
    v1.x /= (s1.x + 1e-16f); v1.y /= (s1.y + 1e-16f);
    v1.z /= (s1.z + 1e-16f); v1.w /= (s1.w + 1e-16f);

    op[0] = v0; op[1] = v1;
}

extern "C" void kernel_launch(void* const* d_in, const int* in_sizes, int n_in,
                              void* d_out, int out_size) {
    const float* q = (const float*)d_in[0];
    const float* k = (const float*)d_in[1];
    const int*   e = (const int*)d_in[2];
    const int*   r = (const int*)d_in[3];
    float* out = (float*)d_out;

    int m = in_sizes[3];                    // r has m elements
    int b = out_size / (m * HEADS);         // output is (b, m, HEADS)
    int n = in_sizes[0] / (b * D);          // q is (b, n, D)

    const int* e0 = e;
    const int* e1 = e + m;

    int seg_count = n * b * HEADS;
    int n16 = (b * n * D) / 8;              // 16-byte half chunks of k
    prep_kernel<<<4000, 256>>>((const float4*)k, e0, m, n16, seg_count);

    scan_kernel<<<1, 1024>>>(n);
    scatter_kernel<<<((m + 3) / 4 + 255) / 256, 256>>>(e0, e1, m);

    int warps = n;                          // one warp per q-node
    passA1_kernel<<<(warps + 7) / 8, 256>>>((const float4*)q, out, n, m, b);

    int mb = m * b;
    int chunks = mb * 2;
    passA2_kernel<<<(chunks + 255) / 256, 256>>>(r, (const float4*)out, m, b);

    passB_kernel<<<(mb + 255) / 256, 256>>>(r, out, m, b);
}